// round 14
// baseline (speedup 1.0000x reference)
#include <cuda_runtime.h>
#include <cuda_bf16.h>
#include <mma.h>
#include <math.h>

using namespace nvcuda;

// Problem constants
#define BATCH   4
#define HH      64
#define WW      64
#define CIN     128
#define FILTERS 128
#define HEADS   8
#define HSIZE   16
#define K0      7
#define K1      7
#define KD      49
#define NPIX    (BATCH*HH*WW)      // 16384
#define NQKV    384                 // q|k|v concat

typedef unsigned long long ull;
typedef unsigned int u32;

// packed f32x2 helpers (sm_100+)
#define FMA2(d, a, b)   asm("fma.rn.f32x2 %0, %1, %2, %0;" : "+l"(d) : "l"(a), "l"(b))
#define MUL2(d, a, b)   asm("mul.rn.f32x2 %0, %1, %2;"     : "=l"(d) : "l"(a), "l"(b))
#define ADD2(d, a, b)   asm("add.rn.f32x2 %0, %1, %2;"     : "=l"(d) : "l"(a), "l"(b))
#define PACK2(d, x, y)  asm("mov.b64 %0, {%1, %2};" : "=l"(d) : "f"(x), "f"(y))
#define UNPK2(lo, hi, s) asm("mov.b64 {%0, %1}, %2;" : "=f"(lo), "=f"(hi) : "l"(s))

__device__ float g_QKV[NPIX * NQKV];

// pre-split bf16 hi/lo storage (4 bf16 per ull)
#define XCHUNKS (NPIX * CIN / 4)          // 524288
#define WCHUNKS (3 * CIN * FILTERS / 4)   // 12288
#define NX2 (XCHUNKS / 2)                 // 262144
#define NW2 (WCHUNKS / 2)                 // 6144
__device__ ull g_Xhi[XCHUNKS];
__device__ ull g_Xlo[XCHUNKS];
__device__ ull g_Whi[WCHUNKS];
__device__ ull g_Wlo[WCHUNKS];

__device__ __forceinline__ void split4(float4 v, ull& hi, ull& lo) {
    __nv_bfloat16 h0 = __float2bfloat16_rn(v.x);
    __nv_bfloat16 h1 = __float2bfloat16_rn(v.y);
    __nv_bfloat16 h2 = __float2bfloat16_rn(v.z);
    __nv_bfloat16 h3 = __float2bfloat16_rn(v.w);
    __nv_bfloat16 l0 = __float2bfloat16_rn(v.x - __bfloat162float(h0));
    __nv_bfloat16 l1 = __float2bfloat16_rn(v.y - __bfloat162float(h1));
    __nv_bfloat16 l2 = __float2bfloat16_rn(v.z - __bfloat162float(h2));
    __nv_bfloat16 l3 = __float2bfloat16_rn(v.w - __bfloat162float(h3));
    unsigned short s0 = *(unsigned short*)&h0, s1 = *(unsigned short*)&h1;
    unsigned short s2 = *(unsigned short*)&h2, s3 = *(unsigned short*)&h3;
    hi = (ull)s0 | ((ull)s1 << 16) | ((ull)s2 << 32) | ((ull)s3 << 48);
    s0 = *(unsigned short*)&l0; s1 = *(unsigned short*)&l1;
    s2 = *(unsigned short*)&l2; s3 = *(unsigned short*)&l3;
    lo = (ull)s0 | ((ull)s1 << 16) | ((ull)s2 << 32) | ((ull)s3 << 48);
}

// ---------------------------------------------------------------------------
// Kernel 0: pre-split X, Wq, Wk, Wv into bf16 hi/lo. MLP=2 per thread.
// ---------------------------------------------------------------------------
__global__ __launch_bounds__(256)
void presplit_kernel(const float* __restrict__ X,
                     const float* __restrict__ Wq,
                     const float* __restrict__ Wk,
                     const float* __restrict__ Wv)
{
    const int t = blockIdx.x * 256 + threadIdx.x;
    if (t < NX2) {
        float4 v0 = ((const float4*)X)[t];
        float4 v1 = ((const float4*)X)[t + NX2];
        ull h0, l0, h1, l1;
        split4(v0, h0, l0);
        split4(v1, h1, l1);
        g_Xhi[t] = h0;       g_Xlo[t] = l0;
        g_Xhi[t + NX2] = h1; g_Xlo[t + NX2] = l1;
    } else {
        const int w = t - NX2;
        if (w < NW2) {
#pragma unroll
            for (int s = 0; s < 2; s++) {
                const int widx = w + s * NW2;
                const int kind = widx / (WCHUNKS / 3);
                const int off  = widx % (WCHUNKS / 3);
                const float* W = (kind == 0) ? Wq : (kind == 1) ? Wk : Wv;
                float4 v = ((const float4*)W)[off];
                ull hi, lo;
                split4(v, hi, lo);
                g_Whi[widx] = hi;
                g_Wlo[widx] = lo;
            }
        }
    }
}

// ---------------------------------------------------------------------------
// Kernel A: pure-bf16 x3 WMMA GEMM, K=128 smem-resident.
// BM=64 x BN=128: smem 104 KB -> 2 blocks/SM, load phase of one block hides
// under the other's HMMA. 256 thr: 8 warps (2 row x 4 col), warp tile 32x32.
// D = Xhi*Whi + Xlo*Whi + Xhi*Wlo  (fp32 accum, rel err ~1.2e-5)
// ---------------------------------------------------------------------------
#define TLD 136
#define A_E (64 * TLD)
#define B_E (128 * TLD)
#define CLD 132
#define GEMM_SMEM ((2 * A_E + 2 * B_E) * 2)   // 104448 B

__global__ __launch_bounds__(256, 2)
void qkv_gemm_kernel(const float* __restrict__ bq,
                     const float* __restrict__ bk,
                     const float* __restrict__ bv,
                     float* __restrict__ QKV)
{
    extern __shared__ __align__(16) char smem[];
    __nv_bfloat16* Ahi = (__nv_bfloat16*)smem;
    __nv_bfloat16* Alo = Ahi + A_E;
    __nv_bfloat16* Bhi = Alo + A_E;
    __nv_bfloat16* Blo = Bhi + B_E;
    float* Cst = (float*)smem;                 // 64 x 132 f32 = 33792 B

    const int bm   = blockIdx.x * 64;
    const int kind = blockIdx.y;               // 0/1/2 -> q/k/v
    const int bn   = kind * 128;
    const float* bias = (kind == 0) ? bq : (kind == 1) ? bk : bv;

    const int tid = threadIdx.x;
    const int wid = tid >> 5;
    const int warp_m = wid & 1;                // 2 row-warps x 32 rows
    const int warp_n = wid >> 1;               // 4 col-warps x 32 cols

    // ---- load A tiles: 64 rows x 16 uint4 (hi+lo) ----
#pragma unroll
    for (int l = 0; l < 4; l++) {
        const int idx = tid + l * 256;         // 0..1023
        const int r = idx >> 4, c = idx & 15;
        const int gsrc = (bm + r) * 16 + c;
        *(uint4*)&Ahi[r * TLD + c * 8] = ((const uint4*)g_Xhi)[gsrc];
        *(uint4*)&Alo[r * TLD + c * 8] = ((const uint4*)g_Xlo)[gsrc];
    }
    // ---- load B tiles: 128 k-rows x 16 uint4 (hi+lo) ----
#pragma unroll
    for (int l = 0; l < 8; l++) {
        const int idx = tid + l * 256;         // 0..2047
        const int r = idx >> 4, c = idx & 15;
        const int wsrc = kind * 2048 + r * 16 + c;
        *(uint4*)&Bhi[r * TLD + c * 8] = ((const uint4*)g_Whi)[wsrc];
        *(uint4*)&Blo[r * TLD + c * 8] = ((const uint4*)g_Wlo)[wsrc];
    }
    __syncthreads();

    wmma::fragment<wmma::accumulator, 16, 16, 16, float> acc[2][2];
#pragma unroll
    for (int i = 0; i < 2; i++)
#pragma unroll
        for (int j = 0; j < 2; j++) wmma::fill_fragment(acc[i][j], 0.f);

#pragma unroll
    for (int ks = 0; ks < CIN; ks += 16) {
        wmma::fragment<wmma::matrix_a, 16, 16, 16, __nv_bfloat16, wmma::row_major> ah[2], al[2];
        wmma::fragment<wmma::matrix_b, 16, 16, 16, __nv_bfloat16, wmma::row_major> bh[2], bl[2];
#pragma unroll
        for (int i = 0; i < 2; i++) {
            const int row = warp_m * 32 + i * 16;
            wmma::load_matrix_sync(ah[i], Ahi + row * TLD + ks, TLD);
            wmma::load_matrix_sync(al[i], Alo + row * TLD + ks, TLD);
        }
#pragma unroll
        for (int j = 0; j < 2; j++) {
            const int col = warp_n * 32 + j * 16;
            wmma::load_matrix_sync(bh[j], Bhi + ks * TLD + col, TLD);
            wmma::load_matrix_sync(bl[j], Blo + ks * TLD + col, TLD);
        }
#pragma unroll
        for (int i = 0; i < 2; i++)
#pragma unroll
            for (int j = 0; j < 2; j++) {
                wmma::mma_sync(acc[i][j], ah[i], bh[j], acc[i][j]);
                wmma::mma_sync(acc[i][j], al[i], bh[j], acc[i][j]);
                wmma::mma_sync(acc[i][j], ah[i], bl[j], acc[i][j]);
            }
    }

    // ---- epilogue: stage via smem (aliases tiles), add bias, store ----
    __syncthreads();
#pragma unroll
    for (int i = 0; i < 2; i++)
#pragma unroll
        for (int j = 0; j < 2; j++)
            wmma::store_matrix_sync(Cst + (warp_m * 32 + i * 16) * CLD + warp_n * 32 + j * 16,
                                    acc[i][j], CLD, wmma::mem_row_major);
    __syncthreads();

#pragma unroll
    for (int l = 0; l < 8; l++) {              // 64 rows x 32 f4 = 2048
        const int idx = tid + l * 256;
        const int r = idx >> 5, c4 = idx & 31;
        float4 v = *(float4*)&Cst[r * CLD + c4 * 4];
        v.x += bias[c4 * 4 + 0];
        v.y += bias[c4 * 4 + 1];
        v.z += bias[c4 * 4 + 2];
        v.w += bias[c4 * 4 + 3];
        *(float4*)(QKV + (size_t)(bm + r) * NQKV + bn + c4 * 4) = v;
    }
}

// ---------------------------------------------------------------------------
// Kernel B: pixel-pair one-pass local attention (proven config, verbatim).
// ---------------------------------------------------------------------------
#define TILE    16
#define HALO    22
#define NHALO   (HALO*HALO)     // 484
#define PSTR    20
#define ATTN_SMEM (2 * NHALO * PSTR * 4)   // 77440 B

__global__ __launch_bounds__(128)
void attn_kernel(const float* __restrict__ QKV,
                 const float* __restrict__ emb0,   // [64,7]
                 const float* __restrict__ emb1,   // [64,7]
                 float* __restrict__ out)
{
    extern __shared__ float sbuf[];
    float* bufK = sbuf;
    float* bufV = sbuf + NHALO * PSTR;

    const int tid = threadIdx.x;
    const int px  = tid & 15;
    const int yp  = tid >> 4;          // 0..7
    const int tx0 = (blockIdx.x & 3) * TILE;
    const int ty0 = (blockIdx.x >> 2) * TILE;
    const int b   = blockIdx.y;
    const int h   = blockIdx.z;

    {
        const int koff = FILTERS + h * HSIZE;
        const int voff = 2 * FILTERS + h * HSIZE;
#pragma unroll
        for (int i = tid; i < NHALO * 4; i += 128) {
            const int hp = i >> 2, c4 = i & 3;
            const int hy = hp / HALO, hx = hp % HALO;
            const int sy = ty0 + hy - 3, sx = tx0 + hx - 3;
            float4 kv = make_float4(0.f, 0.f, 0.f, 0.f);
            float4 vv = make_float4(0.f, 0.f, 0.f, 0.f);
            if ((unsigned)sy < HH && (unsigned)sx < WW) {
                const float* base = QKV + (size_t)(((b * HH) + sy) * WW + sx) * NQKV;
                kv = *(const float4*)(base + koff + c4 * 4);
                vv = *(const float4*)(base + voff + c4 * 4);
            }
            *(float4*)&bufK[hp * PSTR + c4 * 4] = kv;
            *(float4*)&bufV[hp * PSTR + c4 * 4] = vv;
        }
    }

    const int y0   = ty0 + 2 * yp;
    const int pix0 = ((b * HH) + y0) * WW + (tx0 + px);
    const int pix1 = pix0 + WW;

    ull q0[8], q1[8];
    {
        const ulonglong2* qp0 = (const ulonglong2*)(QKV + (size_t)pix0 * NQKV + h * HSIZE);
        const ulonglong2* qp1 = (const ulonglong2*)(QKV + (size_t)pix1 * NQKV + h * HSIZE);
#pragma unroll
        for (int j = 0; j < 4; j++) {
            ulonglong2 t0 = qp0[j];
            ulonglong2 t1 = qp1[j];
            q0[2*j] = t0.x; q0[2*j+1] = t0.y;
            q1[2*j] = t1.x; q1[2*j+1] = t1.y;
        }
    }

    const bool use0 = (h < 4);
    float qe0[7], qe1[7];
    {
        const float* etab = use0 ? (emb0 + h * HSIZE * K0)
                                 : (emb1 + (h * HSIZE - 64) * K1);
        float qf0[16], qf1[16];
#pragma unroll
        for (int j = 0; j < 8; j++) {
            UNPK2(qf0[2*j], qf0[2*j+1], q0[j]);
            UNPK2(qf1[2*j], qf1[2*j+1], q1[j]);
        }
#pragma unroll
        for (int r = 0; r < 7; r++) {
            float s0 = 0.f, s1 = 0.f;
#pragma unroll
            for (int d = 0; d < 16; d++) {
                const float e = etab[d * 7 + r];
                s0 += qf0[d] * e;
                s1 += qf1[d] * e;
            }
            qe0[r] = s0;
            qe1[r] = s1;
        }
    }

    __syncthreads();

    float sum0 = 0.f, sum1 = 0.f;
    ull o0[8], o1[8];
#pragma unroll
    for (int j = 0; j < 8; j++) { o0[j] = 0ull; o1[j] = 0ull; }

#pragma unroll
    for (int dr = 0; dr < 8; dr++) {
#pragma unroll
        for (int dj = 0; dj < 7; dj++) {
            const int eoff = ((2*yp + dr) * HALO + (px + dj)) * PSTR;
            const float* kp = bufK + eoff;
            const float* vp = bufV + eoff;
            ull kr[8], vr[8];
            {
                ulonglong2 t;
                t = *(const ulonglong2*)(kp +  0); kr[0]=t.x; kr[1]=t.y;
                t = *(const ulonglong2*)(kp +  4); kr[2]=t.x; kr[3]=t.y;
                t = *(const ulonglong2*)(kp +  8); kr[4]=t.x; kr[5]=t.y;
                t = *(const ulonglong2*)(kp + 12); kr[6]=t.x; kr[7]=t.y;
                t = *(const ulonglong2*)(vp +  0); vr[0]=t.x; vr[1]=t.y;
                t = *(const ulonglong2*)(vp +  4); vr[2]=t.x; vr[3]=t.y;
                t = *(const ulonglong2*)(vp +  8); vr[4]=t.x; vr[5]=t.y;
                t = *(const ulonglong2*)(vp + 12); vr[6]=t.x; vr[7]=t.y;
            }

            if (dr < 7) {
                ull m0, m1;
                MUL2(m0, q0[0], kr[0]);
                MUL2(m1, q0[1], kr[1]);
                FMA2(m0, q0[2], kr[2]);
                FMA2(m1, q0[3], kr[3]);
                FMA2(m0, q0[4], kr[4]);
                FMA2(m1, q0[5], kr[5]);
                FMA2(m0, q0[6], kr[6]);
                FMA2(m1, q0[7], kr[7]);
                ADD2(m0, m0, m1);
                float lo, hi;
                UNPK2(lo, hi, m0);
                const float s = lo + hi + (use0 ? qe0[dr] : qe0[dj]);
                const float e = __expf(s);
                sum0 += e;
                ull ep; PACK2(ep, e, e);
#pragma unroll
                for (int j = 0; j < 8; j++) FMA2(o0[j], ep, vr[j]);
            }
            if (dr > 0) {
                ull m0, m1;
                MUL2(m0, q1[0], kr[0]);
                MUL2(m1, q1[1], kr[1]);
                FMA2(m0, q1[2], kr[2]);
                FMA2(m1, q1[3], kr[3]);
                FMA2(m0, q1[4], kr[4]);
                FMA2(m1, q1[5], kr[5]);
                FMA2(m0, q1[6], kr[6]);
                FMA2(m1, q1[7], kr[7]);
                ADD2(m0, m0, m1);
                float lo, hi;
                UNPK2(lo, hi, m0);
                const float s = lo + hi + (use0 ? qe1[dr-1] : qe1[dj]);
                const float e = __expf(s);
                sum1 += e;
                ull ep; PACK2(ep, e, e);
#pragma unroll
                for (int j = 0; j < 8; j++) FMA2(o1[j], ep, vr[j]);
            }
        }
    }

    const float inv0 = 1.f / sum0;
    const float inv1 = 1.f / sum1;
    float* op0 = out + (size_t)pix0 * FILTERS + h * HSIZE;
    float* op1 = out + (size_t)pix1 * FILTERS + h * HSIZE;
#pragma unroll
    for (int j = 0; j < 4; j++) {
        float a0, a1, b0, b1;
        UNPK2(a0, a1, o0[2*j]);
        UNPK2(b0, b1, o0[2*j+1]);
        float4 r0 = make_float4(a0*inv0, a1*inv0, b0*inv0, b1*inv0);
        *(float4*)(op0 + j*4) = r0;
        UNPK2(a0, a1, o1[2*j]);
        UNPK2(b0, b1, o1[2*j+1]);
        float4 r1 = make_float4(a0*inv1, a1*inv1, b0*inv1, b1*inv1);
        *(float4*)(op1 + j*4) = r1;
    }
}

// ---------------------------------------------------------------------------
extern "C" void kernel_launch(void* const* d_in, const int* in_sizes, int n_in,
                              void* d_out, int out_size)
{
    const float* x    = (const float*)d_in[0];
    const float* Wq   = (const float*)d_in[1];
    const float* bq   = (const float*)d_in[2];
    const float* Wk   = (const float*)d_in[3];
    const float* bk   = (const float*)d_in[4];
    const float* Wv   = (const float*)d_in[5];
    const float* bv   = (const float*)d_in[6];
    const float* emb0 = (const float*)d_in[7];
    const float* emb1 = (const float*)d_in[8];
    float* out = (float*)d_out;

    float* qkv = nullptr;
    cudaGetSymbolAddress((void**)&qkv, g_QKV);

    cudaFuncSetAttribute(qkv_gemm_kernel,
                         cudaFuncAttributeMaxDynamicSharedMemorySize, GEMM_SMEM);
    cudaFuncSetAttribute(attn_kernel,
                         cudaFuncAttributeMaxDynamicSharedMemorySize, ATTN_SMEM);

    const int total_threads = NX2 + NW2;       // 268288
    presplit_kernel<<<(total_threads + 255) / 256, 256>>>(x, Wq, Wk, Wv);

    dim3 gg(NPIX / 64, 3);                     // (256, 3) = 768 blocks
    qkv_gemm_kernel<<<gg, 256, GEMM_SMEM>>>(bq, bk, bv, qkv);

    dim3 ga(16, BATCH, HEADS);                 // 512 blocks
    attn_kernel<<<ga, 128, ATTN_SMEM>>>(qkv, emb0, emb1, out);
}

// round 15
// speedup vs baseline: 1.0155x; 1.0155x over previous
#include <cuda_runtime.h>
#include <cuda_bf16.h>
#include <mma.h>
#include <math.h>

using namespace nvcuda;

// Problem constants
#define BATCH   4
#define HH      64
#define WW      64
#define CIN     128
#define FILTERS 128
#define HEADS   8
#define HSIZE   16
#define K0      7
#define K1      7
#define KD      49
#define NPIX    (BATCH*HH*WW)      // 16384
#define NQKV    384                 // q|k|v concat

typedef unsigned long long ull;
typedef unsigned int u32;

// packed f32x2 helpers (sm_100+)
#define FMA2(d, a, b)   asm("fma.rn.f32x2 %0, %1, %2, %0;" : "+l"(d) : "l"(a), "l"(b))
#define MUL2(d, a, b)   asm("mul.rn.f32x2 %0, %1, %2;"     : "=l"(d) : "l"(a), "l"(b))
#define ADD2(d, a, b)   asm("add.rn.f32x2 %0, %1, %2;"     : "=l"(d) : "l"(a), "l"(b))
#define PACK2(d, x, y)  asm("mov.b64 %0, {%1, %2};" : "=l"(d) : "f"(x), "f"(y))
#define UNPK2(lo, hi, s) asm("mov.b64 {%0, %1}, %2;" : "=f"(lo), "=f"(hi) : "l"(s))

// cp.async helpers
__device__ __forceinline__ u32 smem_u32(const void* p) {
    u32 a;
    asm("{ .reg .u64 t; cvta.to.shared.u64 t, %1; cvt.u32.u64 %0, t; }"
        : "=r"(a) : "l"(p));
    return a;
}
#define CP_ASYNC16(dst, src) \
    asm volatile("cp.async.cg.shared.global [%0], [%1], 16;" :: "r"(dst), "l"(src))
#define CP_COMMIT() asm volatile("cp.async.commit_group;" ::: "memory")
#define CP_WAIT(n)  asm volatile("cp.async.wait_group %0;" :: "n"(n) : "memory")

__device__ float g_QKV[NPIX * NQKV];

// pre-split bf16 hi/lo storage (4 bf16 per ull)
#define XCHUNKS (NPIX * CIN / 4)          // 524288
#define WCHUNKS (3 * CIN * FILTERS / 4)   // 12288
__device__ ull g_Xhi[XCHUNKS];
__device__ ull g_Xlo[XCHUNKS];
__device__ ull g_Whi[WCHUNKS];
__device__ ull g_Wlo[WCHUNKS];

__device__ __forceinline__ void split4(float4 v, ull& hi, ull& lo) {
    __nv_bfloat16 h0 = __float2bfloat16_rn(v.x);
    __nv_bfloat16 h1 = __float2bfloat16_rn(v.y);
    __nv_bfloat16 h2 = __float2bfloat16_rn(v.z);
    __nv_bfloat16 h3 = __float2bfloat16_rn(v.w);
    __nv_bfloat16 l0 = __float2bfloat16_rn(v.x - __bfloat162float(h0));
    __nv_bfloat16 l1 = __float2bfloat16_rn(v.y - __bfloat162float(h1));
    __nv_bfloat16 l2 = __float2bfloat16_rn(v.z - __bfloat162float(h2));
    __nv_bfloat16 l3 = __float2bfloat16_rn(v.w - __bfloat162float(h3));
    unsigned short s0 = *(unsigned short*)&h0, s1 = *(unsigned short*)&h1;
    unsigned short s2 = *(unsigned short*)&h2, s3 = *(unsigned short*)&h3;
    hi = (ull)s0 | ((ull)s1 << 16) | ((ull)s2 << 32) | ((ull)s3 << 48);
    s0 = *(unsigned short*)&l0; s1 = *(unsigned short*)&l1;
    s2 = *(unsigned short*)&l2; s3 = *(unsigned short*)&l3;
    lo = (ull)s0 | ((ull)s1 << 16) | ((ull)s2 << 32) | ((ull)s3 << 48);
}

// ---------------------------------------------------------------------------
// Kernel 0: pre-split X, Wq, Wk, Wv into bf16 hi/lo (R10 proven version).
// ---------------------------------------------------------------------------
__global__ __launch_bounds__(256)
void presplit_kernel(const float* __restrict__ X,
                     const float* __restrict__ Wq,
                     const float* __restrict__ Wk,
                     const float* __restrict__ Wv)
{
    const int idx = blockIdx.x * 256 + threadIdx.x;
    if (idx < XCHUNKS) {
        float4 v = ((const float4*)X)[idx];
        ull hi, lo;
        split4(v, hi, lo);
        g_Xhi[idx] = hi;
        g_Xlo[idx] = lo;
    } else {
        const int widx = idx - XCHUNKS;
        if (widx < WCHUNKS) {
            const int kind = widx / (WCHUNKS / 3);
            const int off  = widx % (WCHUNKS / 3);
            const float* W = (kind == 0) ? Wq : (kind == 1) ? Wk : Wv;
            float4 v = ((const float4*)W)[off];
            ull hi, lo;
            split4(v, hi, lo);
            g_Whi[widx] = hi;
            g_Wlo[widx] = lo;
        }
    }
}

// ---------------------------------------------------------------------------
// Kernel A: bf16x3 WMMA GEMM, cp.async K-chunk pipeline.
// BM=128 x BN=128 (one kind per blockIdx.y), K in 4 chunks of 32, 2 stages.
// D = Xhi*Whi + Xlo*Whi + Xhi*Wlo  (fp32 accum, rel err ~1.2e-5)
// Stage tiles: A 128rows x 40-elem stride (80B, odd-16B: LDSM clean),
//              B 32krows x 136-elem stride (272B).
// ---------------------------------------------------------------------------
#define CK 32                 // K chunk
#define NCHUNK (CIN / CK)     // 4
#define ALD40 40
#define BLD136 136
#define A_T_B (128 * ALD40 * 2)     // 10240 B per A tile
#define B_T_B (CK * BLD136 * 2)     // 8704 B per B tile
#define STAGE_B (2 * A_T_B + 2 * B_T_B)   // 37888 B
#define CLD 132
#define GEMM_SMEM (2 * STAGE_B)     // 75776 B (Cst 67584 aliases)

__global__ __launch_bounds__(256)
void qkv_gemm_kernel(const float* __restrict__ bq,
                     const float* __restrict__ bk,
                     const float* __restrict__ bv,
                     float* __restrict__ QKV)
{
    extern __shared__ __align__(16) char smem[];

    const int bm   = blockIdx.x * 128;
    const int kind = blockIdx.y;               // 0/1/2 -> q/k/v
    const int bn   = kind * 128;
    const float* bias = (kind == 0) ? bq : (kind == 1) ? bk : bv;

    const int tid = threadIdx.x;
    const int wid = tid >> 5;
    const int warp_m = wid & 3;                // 4 row-warps x 32 rows
    const int warp_n = wid >> 2;               // 2 col-warps x 64 cols

    const u32 sb = smem_u32(smem);

    // issue all cp.async for chunk c into stage s (8 x 16B per thread)
    auto issue_chunk = [&](int c, int s) {
        const u32 st = sb + s * STAGE_B;
        // A tiles: 128 rows x 4 uint4 (hi then lo) -> 1024 copies
        {
            const int i = tid;                 // 0..255
            // each thread: 2 A-rows worth (4 uint4 each across hi+lo)
#pragma unroll
            for (int l = 0; l < 2; l++) {
                const int idx = i + l * 256;   // 0..511 -> (r, u)
                const int r = idx >> 2, u = idx & 3;
                const ull* srch = g_Xhi + ((size_t)(bm + r) * 16 + c * 4 + u) * 2;
                const ull* srcl = g_Xlo + ((size_t)(bm + r) * 16 + c * 4 + u) * 2;
                CP_ASYNC16(st + r * 80 + u * 16, srch);
                CP_ASYNC16(st + A_T_B + r * 80 + u * 16, srcl);
            }
        }
        // B tiles: 32 k-rows x 16 uint4 (hi then lo) -> 1024 copies
        {
#pragma unroll
            for (int l = 0; l < 2; l++) {
                const int idx = tid + l * 256; // 0..511 -> (kr, u)
                const int kr = idx >> 4, u = idx & 15;
                const size_t g = (size_t)kind * 2048 + (size_t)(c * CK + kr) * 16 + u;
                CP_ASYNC16(st + 2 * A_T_B + kr * 272 + u * 16, g_Whi + g * 2);
                CP_ASYNC16(st + 2 * A_T_B + B_T_B + kr * 272 + u * 16, g_Wlo + g * 2);
            }
        }
    };

    // prologue: fill both stages
    issue_chunk(0, 0); CP_COMMIT();
    issue_chunk(1, 1); CP_COMMIT();

    wmma::fragment<wmma::accumulator, 16, 16, 16, float> acc[2][4];
#pragma unroll
    for (int i = 0; i < 2; i++)
#pragma unroll
        for (int j = 0; j < 4; j++) wmma::fill_fragment(acc[i][j], 0.f);

#pragma unroll
    for (int c = 0; c < NCHUNK; c++) {
        const int s = c & 1;
        CP_WAIT(1);
        __syncthreads();

        __nv_bfloat16* Ahi = (__nv_bfloat16*)(smem + s * STAGE_B);
        __nv_bfloat16* Alo = (__nv_bfloat16*)(smem + s * STAGE_B + A_T_B);
        __nv_bfloat16* Bhi = (__nv_bfloat16*)(smem + s * STAGE_B + 2 * A_T_B);
        __nv_bfloat16* Blo = (__nv_bfloat16*)(smem + s * STAGE_B + 2 * A_T_B + B_T_B);

#pragma unroll
        for (int ks = 0; ks < CK; ks += 16) {
            wmma::fragment<wmma::matrix_a, 16, 16, 16, __nv_bfloat16, wmma::row_major> ah[2], al[2];
            wmma::fragment<wmma::matrix_b, 16, 16, 16, __nv_bfloat16, wmma::row_major> bh[4], bl[4];
#pragma unroll
            for (int i = 0; i < 2; i++) {
                const int row = warp_m * 32 + i * 16;
                wmma::load_matrix_sync(ah[i], Ahi + row * ALD40 + ks, ALD40);
                wmma::load_matrix_sync(al[i], Alo + row * ALD40 + ks, ALD40);
            }
#pragma unroll
            for (int j = 0; j < 4; j++) {
                const int col = warp_n * 64 + j * 16;
                wmma::load_matrix_sync(bh[j], Bhi + ks * BLD136 + col, BLD136);
                wmma::load_matrix_sync(bl[j], Blo + ks * BLD136 + col, BLD136);
            }
#pragma unroll
            for (int i = 0; i < 2; i++)
#pragma unroll
                for (int j = 0; j < 4; j++) {
                    wmma::mma_sync(acc[i][j], ah[i], bh[j], acc[i][j]);
                    wmma::mma_sync(acc[i][j], al[i], bh[j], acc[i][j]);
                    wmma::mma_sync(acc[i][j], ah[i], bl[j], acc[i][j]);
                }
        }

        if (c + 2 < NCHUNK) {
            __syncthreads();                  // all warps done reading stage s
            issue_chunk(c + 2, s);
            CP_COMMIT();
        }
    }

    // ---- epilogue: stage via smem (aliases tiles), add bias, store ----
    __syncthreads();
    float* Cst = (float*)smem;
#pragma unroll
    for (int i = 0; i < 2; i++)
#pragma unroll
        for (int j = 0; j < 4; j++)
            wmma::store_matrix_sync(Cst + (warp_m * 32 + i * 16) * CLD + warp_n * 64 + j * 16,
                                    acc[i][j], CLD, wmma::mem_row_major);
    __syncthreads();

#pragma unroll
    for (int l = 0; l < 16; l++) {             // 128 rows x 32 f4
        const int idx = tid + l * 256;
        const int r = idx >> 5, c4 = idx & 31;
        float4 v = *(float4*)&Cst[r * CLD + c4 * 4];
        v.x += bias[c4 * 4 + 0];
        v.y += bias[c4 * 4 + 1];
        v.z += bias[c4 * 4 + 2];
        v.w += bias[c4 * 4 + 3];
        *(float4*)(QKV + (size_t)(bm + r) * NQKV + bn + c4 * 4) = v;
    }
}

// ---------------------------------------------------------------------------
// Kernel B: pixel-pair one-pass local attention (proven config, verbatim).
// ---------------------------------------------------------------------------
#define TILE    16
#define HALO    22
#define NHALO   (HALO*HALO)     // 484
#define PSTR    20
#define ATTN_SMEM (2 * NHALO * PSTR * 4)   // 77440 B

__global__ __launch_bounds__(128)
void attn_kernel(const float* __restrict__ QKV,
                 const float* __restrict__ emb0,   // [64,7]
                 const float* __restrict__ emb1,   // [64,7]
                 float* __restrict__ out)
{
    extern __shared__ float sbuf[];
    float* bufK = sbuf;
    float* bufV = sbuf + NHALO * PSTR;

    const int tid = threadIdx.x;
    const int px  = tid & 15;
    const int yp  = tid >> 4;          // 0..7
    const int tx0 = (blockIdx.x & 3) * TILE;
    const int ty0 = (blockIdx.x >> 2) * TILE;
    const int b   = blockIdx.y;
    const int h   = blockIdx.z;

    {
        const int koff = FILTERS + h * HSIZE;
        const int voff = 2 * FILTERS + h * HSIZE;
#pragma unroll
        for (int i = tid; i < NHALO * 4; i += 128) {
            const int hp = i >> 2, c4 = i & 3;
            const int hy = hp / HALO, hx = hp % HALO;
            const int sy = ty0 + hy - 3, sx = tx0 + hx - 3;
            float4 kv = make_float4(0.f, 0.f, 0.f, 0.f);
            float4 vv = make_float4(0.f, 0.f, 0.f, 0.f);
            if ((unsigned)sy < HH && (unsigned)sx < WW) {
                const float* base = QKV + (size_t)(((b * HH) + sy) * WW + sx) * NQKV;
                kv = *(const float4*)(base + koff + c4 * 4);
                vv = *(const float4*)(base + voff + c4 * 4);
            }
            *(float4*)&bufK[hp * PSTR + c4 * 4] = kv;
            *(float4*)&bufV[hp * PSTR + c4 * 4] = vv;
        }
    }

    const int y0   = ty0 + 2 * yp;
    const int pix0 = ((b * HH) + y0) * WW + (tx0 + px);
    const int pix1 = pix0 + WW;

    ull q0[8], q1[8];
    {
        const ulonglong2* qp0 = (const ulonglong2*)(QKV + (size_t)pix0 * NQKV + h * HSIZE);
        const ulonglong2* qp1 = (const ulonglong2*)(QKV + (size_t)pix1 * NQKV + h * HSIZE);
#pragma unroll
        for (int j = 0; j < 4; j++) {
            ulonglong2 t0 = qp0[j];
            ulonglong2 t1 = qp1[j];
            q0[2*j] = t0.x; q0[2*j+1] = t0.y;
            q1[2*j] = t1.x; q1[2*j+1] = t1.y;
        }
    }

    const bool use0 = (h < 4);
    float qe0[7], qe1[7];
    {
        const float* etab = use0 ? (emb0 + h * HSIZE * K0)
                                 : (emb1 + (h * HSIZE - 64) * K1);
        float qf0[16], qf1[16];
#pragma unroll
        for (int j = 0; j < 8; j++) {
            UNPK2(qf0[2*j], qf0[2*j+1], q0[j]);
            UNPK2(qf1[2*j], qf1[2*j+1], q1[j]);
        }
#pragma unroll
        for (int r = 0; r < 7; r++) {
            float s0 = 0.f, s1 = 0.f;
#pragma unroll
            for (int d = 0; d < 16; d++) {
                const float e = etab[d * 7 + r];
                s0 += qf0[d] * e;
                s1 += qf1[d] * e;
            }
            qe0[r] = s0;
            qe1[r] = s1;
        }
    }

    __syncthreads();

    float sum0 = 0.f, sum1 = 0.f;
    ull o0[8], o1[8];
#pragma unroll
    for (int j = 0; j < 8; j++) { o0[j] = 0ull; o1[j] = 0ull; }

#pragma unroll
    for (int dr = 0; dr < 8; dr++) {
#pragma unroll
        for (int dj = 0; dj < 7; dj++) {
            const int eoff = ((2*yp + dr) * HALO + (px + dj)) * PSTR;
            const float* kp = bufK + eoff;
            const float* vp = bufV + eoff;
            ull kr[8], vr[8];
            {
                ulonglong2 t;
                t = *(const ulonglong2*)(kp +  0); kr[0]=t.x; kr[1]=t.y;
                t = *(const ulonglong2*)(kp +  4); kr[2]=t.x; kr[3]=t.y;
                t = *(const ulonglong2*)(kp +  8); kr[4]=t.x; kr[5]=t.y;
                t = *(const ulonglong2*)(kp + 12); kr[6]=t.x; kr[7]=t.y;
                t = *(const ulonglong2*)(vp +  0); vr[0]=t.x; vr[1]=t.y;
                t = *(const ulonglong2*)(vp +  4); vr[2]=t.x; vr[3]=t.y;
                t = *(const ulonglong2*)(vp +  8); vr[4]=t.x; vr[5]=t.y;
                t = *(const ulonglong2*)(vp + 12); vr[6]=t.x; vr[7]=t.y;
            }

            if (dr < 7) {
                ull m0, m1;
                MUL2(m0, q0[0], kr[0]);
                MUL2(m1, q0[1], kr[1]);
                FMA2(m0, q0[2], kr[2]);
                FMA2(m1, q0[3], kr[3]);
                FMA2(m0, q0[4], kr[4]);
                FMA2(m1, q0[5], kr[5]);
                FMA2(m0, q0[6], kr[6]);
                FMA2(m1, q0[7], kr[7]);
                ADD2(m0, m0, m1);
                float lo, hi;
                UNPK2(lo, hi, m0);
                const float s = lo + hi + (use0 ? qe0[dr] : qe0[dj]);
                const float e = __expf(s);
                sum0 += e;
                ull ep; PACK2(ep, e, e);
#pragma unroll
                for (int j = 0; j < 8; j++) FMA2(o0[j], ep, vr[j]);
            }
            if (dr > 0) {
                ull m0, m1;
                MUL2(m0, q1[0], kr[0]);
                MUL2(m1, q1[1], kr[1]);
                FMA2(m0, q1[2], kr[2]);
                FMA2(m1, q1[3], kr[3]);
                FMA2(m0, q1[4], kr[4]);
                FMA2(m1, q1[5], kr[5]);
                FMA2(m0, q1[6], kr[6]);
                FMA2(m1, q1[7], kr[7]);
                ADD2(m0, m0, m1);
                float lo, hi;
                UNPK2(lo, hi, m0);
                const float s = lo + hi + (use0 ? qe1[dr-1] : qe1[dj]);
                const float e = __expf(s);
                sum1 += e;
                ull ep; PACK2(ep, e, e);
#pragma unroll
                for (int j = 0; j < 8; j++) FMA2(o1[j], ep, vr[j]);
            }
        }
    }

    const float inv0 = 1.f / sum0;
    const float inv1 = 1.f / sum1;
    float* op0 = out + (size_t)pix0 * FILTERS + h * HSIZE;
    float* op1 = out + (size_t)pix1 * FILTERS + h * HSIZE;
#pragma unroll
    for (int j = 0; j < 4; j++) {
        float a0, a1, b0, b1;
        UNPK2(a0, a1, o0[2*j]);
        UNPK2(b0, b1, o0[2*j+1]);
        float4 r0 = make_float4(a0*inv0, a1*inv0, b0*inv0, b1*inv0);
        *(float4*)(op0 + j*4) = r0;
        UNPK2(a0, a1, o1[2*j]);
        UNPK2(b0, b1, o1[2*j+1]);
        float4 r1 = make_float4(a0*inv1, a1*inv1, b0*inv1, b1*inv1);
        *(float4*)(op1 + j*4) = r1;
    }
}

// ---------------------------------------------------------------------------
extern "C" void kernel_launch(void* const* d_in, const int* in_sizes, int n_in,
                              void* d_out, int out_size)
{
    const float* x    = (const float*)d_in[0];
    const float* Wq   = (const float*)d_in[1];
    const float* bq   = (const float*)d_in[2];
    const float* Wk   = (const float*)d_in[3];
    const float* bk   = (const float*)d_in[4];
    const float* Wv   = (const float*)d_in[5];
    const float* bv   = (const float*)d_in[6];
    const float* emb0 = (const float*)d_in[7];
    const float* emb1 = (const float*)d_in[8];
    float* out = (float*)d_out;

    float* qkv = nullptr;
    cudaGetSymbolAddress((void**)&qkv, g_QKV);

    cudaFuncSetAttribute(qkv_gemm_kernel,
                         cudaFuncAttributeMaxDynamicSharedMemorySize, GEMM_SMEM);
    cudaFuncSetAttribute(attn_kernel,
                         cudaFuncAttributeMaxDynamicSharedMemorySize, ATTN_SMEM);

    const int total_chunks = XCHUNKS + WCHUNKS;
    presplit_kernel<<<(total_chunks + 255) / 256, 256>>>(x, Wq, Wk, Wv);

    dim3 gg(NPIX / 128, 3);
    qkv_gemm_kernel<<<gg, 256, GEMM_SMEM>>>(bq, bk, bv, qkv);

    dim3 ga(16, BATCH, HEADS);         // 512 blocks
    attn_kernel<<<ga, 128, ATTN_SMEM>>>(qkv, emb0, emb1, out);
}

// round 16
// speedup vs baseline: 1.0526x; 1.0365x over previous
#include <cuda_runtime.h>
#include <cuda_bf16.h>
#include <mma.h>
#include <math.h>

using namespace nvcuda;

// Problem constants
#define BATCH   4
#define HH      64
#define WW      64
#define CIN     128
#define FILTERS 128
#define HEADS   8
#define HSIZE   16
#define K0      7
#define K1      7
#define KD      49
#define NPIX    (BATCH*HH*WW)      // 16384
#define NQKV    384                 // q|k|v concat

typedef unsigned long long ull;
typedef unsigned int u32;

// packed f32x2 helpers (sm_100+)
#define FMA2(d, a, b)   asm("fma.rn.f32x2 %0, %1, %2, %0;" : "+l"(d) : "l"(a), "l"(b))
#define MUL2(d, a, b)   asm("mul.rn.f32x2 %0, %1, %2;"     : "=l"(d) : "l"(a), "l"(b))
#define ADD2(d, a, b)   asm("add.rn.f32x2 %0, %1, %2;"     : "=l"(d) : "l"(a), "l"(b))
#define PACK2(d, x, y)  asm("mov.b64 %0, {%1, %2};" : "=l"(d) : "f"(x), "f"(y))
#define UNPK2(lo, hi, s) asm("mov.b64 {%0, %1}, %2;" : "=f"(lo), "=f"(hi) : "l"(s))

__device__ float g_QKV[NPIX * NQKV];

// pre-split bf16 hi/lo storage (4 bf16 per ull)
#define XCHUNKS (NPIX * CIN / 4)          // 524288
#define WCHUNKS (3 * CIN * FILTERS / 4)   // 12288
__device__ ull g_Xhi[XCHUNKS];
__device__ ull g_Xlo[XCHUNKS];
__device__ ull g_Whi[WCHUNKS];
__device__ ull g_Wlo[WCHUNKS];

__device__ __forceinline__ void split4(float4 v, ull& hi, ull& lo) {
    __nv_bfloat16 h0 = __float2bfloat16_rn(v.x);
    __nv_bfloat16 h1 = __float2bfloat16_rn(v.y);
    __nv_bfloat16 h2 = __float2bfloat16_rn(v.z);
    __nv_bfloat16 h3 = __float2bfloat16_rn(v.w);
    __nv_bfloat16 l0 = __float2bfloat16_rn(v.x - __bfloat162float(h0));
    __nv_bfloat16 l1 = __float2bfloat16_rn(v.y - __bfloat162float(h1));
    __nv_bfloat16 l2 = __float2bfloat16_rn(v.z - __bfloat162float(h2));
    __nv_bfloat16 l3 = __float2bfloat16_rn(v.w - __bfloat162float(h3));
    unsigned short s0 = *(unsigned short*)&h0, s1 = *(unsigned short*)&h1;
    unsigned short s2 = *(unsigned short*)&h2, s3 = *(unsigned short*)&h3;
    hi = (ull)s0 | ((ull)s1 << 16) | ((ull)s2 << 32) | ((ull)s3 << 48);
    s0 = *(unsigned short*)&l0; s1 = *(unsigned short*)&l1;
    s2 = *(unsigned short*)&l2; s3 = *(unsigned short*)&l3;
    lo = (ull)s0 | ((ull)s1 << 16) | ((ull)s2 << 32) | ((ull)s3 << 48);
}

// ---------------------------------------------------------------------------
// Kernel 0: pre-split X, Wq, Wk, Wv. Each thread: 2 CONTIGUOUS chunks ->
// 2x LDG.128 in, 2x STG.128 out per array (16B stores).
// ---------------------------------------------------------------------------
#define NXP (XCHUNKS / 2)     // 262144 X pair-threads
#define NWP (WCHUNKS / 2)     // 6144 W pair-threads

__global__ __launch_bounds__(256)
void presplit_kernel(const float* __restrict__ X,
                     const float* __restrict__ Wq,
                     const float* __restrict__ Wk,
                     const float* __restrict__ Wv)
{
    const int t = blockIdx.x * 256 + threadIdx.x;
    if (t < NXP) {
        const int c0 = 2 * t;
        float4 v0 = ((const float4*)X)[c0];
        float4 v1 = ((const float4*)X)[c0 + 1];
        ull h0, l0, h1, l1;
        split4(v0, h0, l0);
        split4(v1, h1, l1);
        *(ulonglong2*)&g_Xhi[c0] = make_ulonglong2(h0, h1);
        *(ulonglong2*)&g_Xlo[c0] = make_ulonglong2(l0, l1);
    } else {
        const int w = t - NXP;
        if (w < NWP) {
            const int c0 = 2 * w;              // pairs never straddle kinds (4096-even)
            const int kind = c0 / (WCHUNKS / 3);
            const int off  = c0 % (WCHUNKS / 3);
            const float* W = (kind == 0) ? Wq : (kind == 1) ? Wk : Wv;
            float4 v0 = ((const float4*)W)[off];
            float4 v1 = ((const float4*)W)[off + 1];
            ull h0, l0, h1, l1;
            split4(v0, h0, l0);
            split4(v1, h1, l1);
            *(ulonglong2*)&g_Whi[c0] = make_ulonglong2(h0, h1);
            *(ulonglong2*)&g_Wlo[c0] = make_ulonglong2(l0, l1);
        }
    }
}

// ---------------------------------------------------------------------------
// Kernel A: persistent-A bf16x3 WMMA GEMM.
// grid(128): one block per 128-row M tile; A hi/lo loaded ONCE, then loop
// kind=0..2 reloading only B. One full wave (128 <= 148 SMs), no ragged tail.
// D = Xhi*Whi + Xlo*Whi + Xhi*Wlo  (fp32 accum, rel err ~1.2e-5)
// smem: A hi/lo (69632 B) + B hi/lo (69632 B); Cst aliases the B region.
// ---------------------------------------------------------------------------
#define TLD 136
#define TILE_E (128 * TLD)
#define A_REGION (2 * TILE_E * 2)          // 69632 B
#define CLD 132
#define GEMM_SMEM (4 * TILE_E * 2)         // 139264 B

__global__ __launch_bounds__(256)
void qkv_gemm_kernel(const float* __restrict__ bq,
                     const float* __restrict__ bk,
                     const float* __restrict__ bv,
                     float* __restrict__ QKV)
{
    extern __shared__ __align__(16) char smem[];
    __nv_bfloat16* Ahi = (__nv_bfloat16*)smem;
    __nv_bfloat16* Alo = Ahi + TILE_E;
    __nv_bfloat16* Bhi = Alo + TILE_E;               // B region start
    __nv_bfloat16* Blo = Bhi + TILE_E;
    float* Cst = (float*)(smem + A_REGION);          // aliases B region

    const int bm = blockIdx.x * 128;
    const int tid = threadIdx.x;
    const int wid = tid >> 5;
    const int warp_m = wid & 3;
    const int warp_n = wid >> 2;

    // ---- load A hi/lo ONCE ----
#pragma unroll
    for (int l = 0; l < 8; l++) {
        const int idx = tid + l * 256;
        const int r = idx >> 4, c = idx & 15;
        const int gsrc = (bm + r) * 16 + c;
        *(uint4*)&Ahi[r * TLD + c * 8] = ((const uint4*)g_Xhi)[gsrc];
        *(uint4*)&Alo[r * TLD + c * 8] = ((const uint4*)g_Xlo)[gsrc];
    }

    for (int kind = 0; kind < 3; kind++) {
        const float* bias = (kind == 0) ? bq : (kind == 1) ? bk : bv;

        // ---- load B hi/lo for this kind ----
#pragma unroll
        for (int l = 0; l < 8; l++) {
            const int idx = tid + l * 256;
            const int r = idx >> 4, c = idx & 15;
            const int wsrc = kind * 2048 + r * 16 + c;
            *(uint4*)&Bhi[r * TLD + c * 8] = ((const uint4*)g_Whi)[wsrc];
            *(uint4*)&Blo[r * TLD + c * 8] = ((const uint4*)g_Wlo)[wsrc];
        }
        __syncthreads();

        wmma::fragment<wmma::accumulator, 16, 16, 16, float> acc[2][4];
#pragma unroll
        for (int i = 0; i < 2; i++)
#pragma unroll
            for (int j = 0; j < 4; j++) wmma::fill_fragment(acc[i][j], 0.f);

#pragma unroll
        for (int ks = 0; ks < CIN; ks += 16) {
            wmma::fragment<wmma::matrix_a, 16, 16, 16, __nv_bfloat16, wmma::row_major> ah[2], al[2];
            wmma::fragment<wmma::matrix_b, 16, 16, 16, __nv_bfloat16, wmma::row_major> bh[4], bl[4];
#pragma unroll
            for (int i = 0; i < 2; i++) {
                const int row = warp_m * 32 + i * 16;
                wmma::load_matrix_sync(ah[i], Ahi + row * TLD + ks, TLD);
                wmma::load_matrix_sync(al[i], Alo + row * TLD + ks, TLD);
            }
#pragma unroll
            for (int j = 0; j < 4; j++) {
                const int col = warp_n * 64 + j * 16;
                wmma::load_matrix_sync(bh[j], Bhi + ks * TLD + col, TLD);
                wmma::load_matrix_sync(bl[j], Blo + ks * TLD + col, TLD);
            }
#pragma unroll
            for (int i = 0; i < 2; i++)
#pragma unroll
                for (int j = 0; j < 4; j++) {
                    wmma::mma_sync(acc[i][j], ah[i], bh[j], acc[i][j]);
                    wmma::mma_sync(acc[i][j], al[i], bh[j], acc[i][j]);
                    wmma::mma_sync(acc[i][j], ah[i], bl[j], acc[i][j]);
                }
        }

        // ---- epilogue into B region (B dead; reloaded next kind) ----
        __syncthreads();
#pragma unroll
        for (int i = 0; i < 2; i++)
#pragma unroll
            for (int j = 0; j < 4; j++)
                wmma::store_matrix_sync(Cst + (warp_m * 32 + i * 16) * CLD + warp_n * 64 + j * 16,
                                        acc[i][j], CLD, wmma::mem_row_major);
        __syncthreads();

#pragma unroll
        for (int l = 0; l < 16; l++) {
            const int idx = tid + l * 256;
            const int r = idx >> 5, c4 = idx & 31;
            float4 v = *(float4*)&Cst[r * CLD + c4 * 4];
            v.x += bias[c4 * 4 + 0];
            v.y += bias[c4 * 4 + 1];
            v.z += bias[c4 * 4 + 2];
            v.w += bias[c4 * 4 + 3];
            *(float4*)(QKV + (size_t)(bm + r) * NQKV + kind * 128 + c4 * 4) = v;
        }
        __syncthreads();     // Cst reads done before next kind's B load
    }
}

// ---------------------------------------------------------------------------
// Kernel B: pixel-pair one-pass local attention (proven config, verbatim).
// ---------------------------------------------------------------------------
#define TILE    16
#define HALO    22
#define NHALO   (HALO*HALO)     // 484
#define PSTR    20
#define ATTN_SMEM (2 * NHALO * PSTR * 4)   // 77440 B

__global__ __launch_bounds__(128)
void attn_kernel(const float* __restrict__ QKV,
                 const float* __restrict__ emb0,   // [64,7]
                 const float* __restrict__ emb1,   // [64,7]
                 float* __restrict__ out)
{
    extern __shared__ float sbuf[];
    float* bufK = sbuf;
    float* bufV = sbuf + NHALO * PSTR;

    const int tid = threadIdx.x;
    const int px  = tid & 15;
    const int yp  = tid >> 4;          // 0..7
    const int tx0 = (blockIdx.x & 3) * TILE;
    const int ty0 = (blockIdx.x >> 2) * TILE;
    const int b   = blockIdx.y;
    const int h   = blockIdx.z;

    {
        const int koff = FILTERS + h * HSIZE;
        const int voff = 2 * FILTERS + h * HSIZE;
#pragma unroll
        for (int i = tid; i < NHALO * 4; i += 128) {
            const int hp = i >> 2, c4 = i & 3;
            const int hy = hp / HALO, hx = hp % HALO;
            const int sy = ty0 + hy - 3, sx = tx0 + hx - 3;
            float4 kv = make_float4(0.f, 0.f, 0.f, 0.f);
            float4 vv = make_float4(0.f, 0.f, 0.f, 0.f);
            if ((unsigned)sy < HH && (unsigned)sx < WW) {
                const float* base = QKV + (size_t)(((b * HH) + sy) * WW + sx) * NQKV;
                kv = *(const float4*)(base + koff + c4 * 4);
                vv = *(const float4*)(base + voff + c4 * 4);
            }
            *(float4*)&bufK[hp * PSTR + c4 * 4] = kv;
            *(float4*)&bufV[hp * PSTR + c4 * 4] = vv;
        }
    }

    const int y0   = ty0 + 2 * yp;
    const int pix0 = ((b * HH) + y0) * WW + (tx0 + px);
    const int pix1 = pix0 + WW;

    ull q0[8], q1[8];
    {
        const ulonglong2* qp0 = (const ulonglong2*)(QKV + (size_t)pix0 * NQKV + h * HSIZE);
        const ulonglong2* qp1 = (const ulonglong2*)(QKV + (size_t)pix1 * NQKV + h * HSIZE);
#pragma unroll
        for (int j = 0; j < 4; j++) {
            ulonglong2 t0 = qp0[j];
            ulonglong2 t1 = qp1[j];
            q0[2*j] = t0.x; q0[2*j+1] = t0.y;
            q1[2*j] = t1.x; q1[2*j+1] = t1.y;
        }
    }

    const bool use0 = (h < 4);
    float qe0[7], qe1[7];
    {
        const float* etab = use0 ? (emb0 + h * HSIZE * K0)
                                 : (emb1 + (h * HSIZE - 64) * K1);
        float qf0[16], qf1[16];
#pragma unroll
        for (int j = 0; j < 8; j++) {
            UNPK2(qf0[2*j], qf0[2*j+1], q0[j]);
            UNPK2(qf1[2*j], qf1[2*j+1], q1[j]);
        }
#pragma unroll
        for (int r = 0; r < 7; r++) {
            float s0 = 0.f, s1 = 0.f;
#pragma unroll
            for (int d = 0; d < 16; d++) {
                const float e = etab[d * 7 + r];
                s0 += qf0[d] * e;
                s1 += qf1[d] * e;
            }
            qe0[r] = s0;
            qe1[r] = s1;
        }
    }

    __syncthreads();

    float sum0 = 0.f, sum1 = 0.f;
    ull o0[8], o1[8];
#pragma unroll
    for (int j = 0; j < 8; j++) { o0[j] = 0ull; o1[j] = 0ull; }

#pragma unroll
    for (int dr = 0; dr < 8; dr++) {
#pragma unroll
        for (int dj = 0; dj < 7; dj++) {
            const int eoff = ((2*yp + dr) * HALO + (px + dj)) * PSTR;
            const float* kp = bufK + eoff;
            const float* vp = bufV + eoff;
            ull kr[8], vr[8];
            {
                ulonglong2 t;
                t = *(const ulonglong2*)(kp +  0); kr[0]=t.x; kr[1]=t.y;
                t = *(const ulonglong2*)(kp +  4); kr[2]=t.x; kr[3]=t.y;
                t = *(const ulonglong2*)(kp +  8); kr[4]=t.x; kr[5]=t.y;
                t = *(const ulonglong2*)(kp + 12); kr[6]=t.x; kr[7]=t.y;
                t = *(const ulonglong2*)(vp +  0); vr[0]=t.x; vr[1]=t.y;
                t = *(const ulonglong2*)(vp +  4); vr[2]=t.x; vr[3]=t.y;
                t = *(const ulonglong2*)(vp +  8); vr[4]=t.x; vr[5]=t.y;
                t = *(const ulonglong2*)(vp + 12); vr[6]=t.x; vr[7]=t.y;
            }

            if (dr < 7) {
                ull m0, m1;
                MUL2(m0, q0[0], kr[0]);
                MUL2(m1, q0[1], kr[1]);
                FMA2(m0, q0[2], kr[2]);
                FMA2(m1, q0[3], kr[3]);
                FMA2(m0, q0[4], kr[4]);
                FMA2(m1, q0[5], kr[5]);
                FMA2(m0, q0[6], kr[6]);
                FMA2(m1, q0[7], kr[7]);
                ADD2(m0, m0, m1);
                float lo, hi;
                UNPK2(lo, hi, m0);
                const float s = lo + hi + (use0 ? qe0[dr] : qe0[dj]);
                const float e = __expf(s);
                sum0 += e;
                ull ep; PACK2(ep, e, e);
#pragma unroll
                for (int j = 0; j < 8; j++) FMA2(o0[j], ep, vr[j]);
            }
            if (dr > 0) {
                ull m0, m1;
                MUL2(m0, q1[0], kr[0]);
                MUL2(m1, q1[1], kr[1]);
                FMA2(m0, q1[2], kr[2]);
                FMA2(m1, q1[3], kr[3]);
                FMA2(m0, q1[4], kr[4]);
                FMA2(m1, q1[5], kr[5]);
                FMA2(m0, q1[6], kr[6]);
                FMA2(m1, q1[7], kr[7]);
                ADD2(m0, m0, m1);
                float lo, hi;
                UNPK2(lo, hi, m0);
                const float s = lo + hi + (use0 ? qe1[dr-1] : qe1[dj]);
                const float e = __expf(s);
                sum1 += e;
                ull ep; PACK2(ep, e, e);
#pragma unroll
                for (int j = 0; j < 8; j++) FMA2(o1[j], ep, vr[j]);
            }
        }
    }

    const float inv0 = 1.f / sum0;
    const float inv1 = 1.f / sum1;
    float* op0 = out + (size_t)pix0 * FILTERS + h * HSIZE;
    float* op1 = out + (size_t)pix1 * FILTERS + h * HSIZE;
#pragma unroll
    for (int j = 0; j < 4; j++) {
        float a0, a1, b0, b1;
        UNPK2(a0, a1, o0[2*j]);
        UNPK2(b0, b1, o0[2*j+1]);
        float4 r0 = make_float4(a0*inv0, a1*inv0, b0*inv0, b1*inv0);
        *(float4*)(op0 + j*4) = r0;
        UNPK2(a0, a1, o1[2*j]);
        UNPK2(b0, b1, o1[2*j+1]);
        float4 r1 = make_float4(a0*inv1, a1*inv1, b0*inv1, b1*inv1);
        *(float4*)(op1 + j*4) = r1;
    }
}

// ---------------------------------------------------------------------------
extern "C" void kernel_launch(void* const* d_in, const int* in_sizes, int n_in,
                              void* d_out, int out_size)
{
    const float* x    = (const float*)d_in[0];
    const float* Wq   = (const float*)d_in[1];
    const float* bq   = (const float*)d_in[2];
    const float* Wk   = (const float*)d_in[3];
    const float* bk   = (const float*)d_in[4];
    const float* Wv   = (const float*)d_in[5];
    const float* bv   = (const float*)d_in[6];
    const float* emb0 = (const float*)d_in[7];
    const float* emb1 = (const float*)d_in[8];
    float* out = (float*)d_out;

    float* qkv = nullptr;
    cudaGetSymbolAddress((void**)&qkv, g_QKV);

    cudaFuncSetAttribute(qkv_gemm_kernel,
                         cudaFuncAttributeMaxDynamicSharedMemorySize, GEMM_SMEM);
    cudaFuncSetAttribute(attn_kernel,
                         cudaFuncAttributeMaxDynamicSharedMemorySize, ATTN_SMEM);

    const int total_threads = NXP + NWP;       // 268288
    presplit_kernel<<<(total_threads + 255) / 256, 256>>>(x, Wq, Wk, Wv);

    qkv_gemm_kernel<<<128, 256, GEMM_SMEM>>>(bq, bk, bv, qkv);

    dim3 ga(16, BATCH, HEADS);                 // 512 blocks
    attn_kernel<<<ga, 128, ATTN_SMEM>>>(qkv, emb0, emb1, out);
}